// round 13
// baseline (speedup 1.0000x reference)
#include <cuda_runtime.h>
#include <cstdint>

// FPS B=16, N=65536, S=2048, out = coords of selected (B,S,3) f32.
// R13: NO clusters. 16 CTAs/batch x 16 batches = 256 CTAs of 256 threads,
// 2 co-resident CTAs per SM from different batches -> exchange latency of one
// batch hides behind the other batch's compute (hardware-interleaved).
// Exchange via __device__ global slots: release-store iteration tag,
// acquire-load polling. Monotonic tags => correct across graph replays, no
// resets. Hot loop identical to R9: negated coords SoA in smem -> ulonglong2
// -> packed add/mul.rn.f32x2 (per-lane IEEE RN, bit-identical); value-only
// max (redux.sync) + parallel-min rescan for exact first-index argmax;
// split-u32 redux CTA + cross-CTA reduce (exact global first-index).

#define NBATCH   16
#define NPTS     65536
#define NSAMP    2048
#define CPB      16                   // CTAs per batch
#define NPC      (NPTS / CPB)         // 4096
#define THREADS  256
#define NWARPS   (THREADS / 32)       // 8
#define PPT      (NPC / THREADS)      // 16
#define GROUPS   (PPT / 4)            // 4

typedef unsigned long long u64;

// 32-byte global exchange slot. tag written LAST with release semantics.
struct __align__(16) GSlot {
    u64      key;    // (valBits<<32) | ~gidx
    u64      xy;     // packed selected x,y
    float    z;
    unsigned pad0;
    unsigned tag;    // = it+1 when slot valid for iteration it
    unsigned pad1;
};

__device__ GSlot g_slots[NBATCH][2][CPB];   // zero-init: tag=0

struct __align__(16) Smem {
    float x[NPC];                // negated coords
    float y[NPC];
    float z[NPC];
    u64   wkey[NWARPS];          // per-warp packed (valBits<<32)|~localIdx
    float bc[4];                 // broadcast: selected coords
};

__device__ __forceinline__ u64 pk2(float lo, float hi) {
    u64 r; asm("mov.b64 %0, {%1, %2};" : "=l"(r) : "f"(lo), "f"(hi)); return r;
}
__device__ __forceinline__ void upk2(float& lo, float& hi, u64 v) {
    asm("mov.b64 {%0, %1}, %2;" : "=f"(lo), "=f"(hi) : "l"(v));
}
__device__ __forceinline__ u64 add2(u64 a, u64 b) {
    u64 r; asm("add.rn.f32x2 %0, %1, %2;" : "=l"(r) : "l"(a), "l"(b)); return r;
}
__device__ __forceinline__ u64 mul2(u64 a, u64 b) {
    u64 r; asm("mul.rn.f32x2 %0, %1, %2;" : "=l"(r) : "l"(a), "l"(b)); return r;
}
__device__ __forceinline__ unsigned redux_max(unsigned v) {
    unsigned r; asm("redux.sync.max.u32 %0, %1, 0xffffffff;" : "=r"(r) : "r"(v)); return r;
}
__device__ __forceinline__ unsigned redux_min(unsigned v) {
    unsigned r; asm("redux.sync.min.u32 %0, %1, 0xffffffff;" : "=r"(r) : "r"(v)); return r;
}

__global__ void __launch_bounds__(THREADS, 2)
fps_kernel(const float* __restrict__ pc, float* __restrict__ out)
{
    extern __shared__ char smraw[];
    Smem& s = *reinterpret_cast<Smem*>(smraw);

    const int tid  = threadIdx.x;
    const int lane = tid & 31;
    const int warp = tid >> 5;
    const int cta  = blockIdx.x & (CPB - 1);   // CTA index within batch
    const int b    = blockIdx.x >> 4;          // batch

    const float* __restrict__ base = pc + (size_t)b * NPTS * 3;

    // ---- prologue: stage NEGATED coords as SoA ----
    for (int i = tid; i < NPC; i += THREADS) {
        int gi = cta * NPC + i;
        s.x[i] = -base[gi * 3 + 0];
        s.y[i] = -base[gi * 3 + 1];
        s.z[i] = -base[gi * 3 + 2];
    }

    float closest[PPT];
    #pragma unroll
    for (int i = 0; i < PPT; i++) closest[i] = __int_as_float(0x7f800000);

    float sx = base[0], sy = base[1], sz = base[2];   // initial selection: point 0

    __syncthreads();

    for (int it = 0; it < NSAMP; ++it) {
        const int p = it & 1;
        const unsigned want = (unsigned)(it + 1);

        // ---- distance update + running min; value-only max (packed f32x2) ----
        u64 sxx = pk2(sx, sx), syy = pk2(sy, sy), szz = pk2(sz, sz);
        float vmax = 0.0f;
        #pragma unroll
        for (int g = 0; g < GROUPS; ++g) {
            const int bi = g * (THREADS * 4) + tid * 4;
            ulonglong2 X = *reinterpret_cast<const ulonglong2*>(&s.x[bi]);
            ulonglong2 Y = *reinterpret_cast<const ulonglong2*>(&s.y[bi]);
            ulonglong2 Z = *reinterpret_cast<const ulonglong2*>(&s.z[bi]);
            {   // points 0,1 : d = (s + (-x))^2 + (s + (-y))^2 + (s + (-z))^2
                u64 dx = add2(sxx, X.x);
                u64 dy = add2(syy, Y.x);
                u64 dz = add2(szz, Z.x);
                u64 d  = add2(add2(mul2(dx, dx), mul2(dy, dy)), mul2(dz, dz));
                float d0, d1; upk2(d0, d1, d);
                float c0 = fminf(closest[g*4+0], d0); closest[g*4+0] = c0;
                float c1 = fminf(closest[g*4+1], d1); closest[g*4+1] = c1;
                vmax = fmaxf(vmax, c0); vmax = fmaxf(vmax, c1);
            }
            {   // points 2,3
                u64 dx = add2(sxx, X.y);
                u64 dy = add2(syy, Y.y);
                u64 dz = add2(szz, Z.y);
                u64 d  = add2(add2(mul2(dx, dx), mul2(dy, dy)), mul2(dz, dz));
                float d0, d1; upk2(d0, d1, d);
                float c0 = fminf(closest[g*4+2], d0); closest[g*4+2] = c0;
                float c1 = fminf(closest[g*4+3], d1); closest[g*4+3] = c1;
                vmax = fmaxf(vmax, c0); vmax = fmaxf(vmax, c1);
            }
        }

        // ---- warp reduce: value max + exact first local index ----
        const unsigned wmax = redux_max(__float_as_uint(vmax));
        unsigned my = 0xffffffffu;
        #pragma unroll
        for (int g = 0; g < GROUPS; ++g) {
            #pragma unroll
            for (int j = 0; j < 4; ++j) {
                unsigned cand = (unsigned)(g * (THREADS * 4) + tid * 4 + j);
                if (__float_as_uint(closest[g*4+j]) == wmax)
                    my = (cand < my) ? cand : my;
            }
        }
        const unsigned wmin = redux_min(my);
        if (lane == 0)
            s.wkey[warp] = ((u64)wmax << 32) | (u64)(unsigned)(~wmin);
        __syncthreads();

        // ---- warp 0: CTA reduce, publish, poll peers, cross-CTA reduce ----
        if (warp == 0) {
            // CTA reduce over 8 warp keys (split-u32 redux)
            u64 wk = (lane < NWARPS) ? s.wkey[lane] : 0ull;
            unsigned vhi = (unsigned)(wk >> 32);
            unsigned vlo = (unsigned)wk;                          // ~localIdx
            unsigned Vmax = redux_max(vhi);
            unsigned nli  = redux_max((vhi == Vmax) ? vlo : 0u);  // max ~idx = min idx

            // lane 0 publishes this CTA's best to its global slot
            if (lane == 0) {
                unsigned li   = ~nli;
                unsigned gidx = (unsigned)cta * NPC + li;
                u64 ckey = ((u64)Vmax << 32) | (u64)(unsigned)(~gidx);
                float cx = -s.x[li], cy = -s.y[li], cz = -s.z[li];   // un-negate
                u64 xy = pk2(cx, cy);
                GSlot* sl = &g_slots[b][p][cta];
                asm volatile("st.global.b64 [%0], %1;" :: "l"(&sl->key), "l"(ckey) : "memory");
                asm volatile("st.global.b64 [%0], %1;" :: "l"(&sl->xy),  "l"(xy)   : "memory");
                asm volatile("st.global.b32 [%0], %1;" :: "l"(&sl->z),   "f"(cz)   : "memory");
                asm volatile("st.release.gpu.global.b32 [%0], %1;"
                             :: "l"(&sl->tag), "r"(want) : "memory");
            }

            // lanes 0..15 poll their peer slot's tag (acquire), then read slot
            u64 kkey = 0ull, kxy = 0ull;
            float kz = 0.0f;
            if (lane < CPB) {
                GSlot* sl = &g_slots[b][p][lane];
                unsigned t;
                do {
                    asm volatile("ld.acquire.gpu.global.b32 %0, [%1];"
                                 : "=r"(t) : "l"(&sl->tag) : "memory");
                } while (t != want);
                asm volatile("ld.global.b64 %0, [%1];" : "=l"(kkey) : "l"(&sl->key) : "memory");
                asm volatile("ld.global.b64 %0, [%1];" : "=l"(kxy)  : "l"(&sl->xy)  : "memory");
                asm volatile("ld.global.b32 %0, [%1];" : "=f"(kz)   : "l"(&sl->z)   : "memory");
            }
            __syncwarp();

            // cross-CTA reduce over 16 keys (split-u32 redux, exact)
            unsigned khi = (unsigned)(kkey >> 32);
            unsigned klo = (unsigned)kkey;
            unsigned GV  = redux_max(khi);
            unsigned GL  = redux_max((khi == GV) ? klo : 0u);
            int winner   = (lane < CPB && khi == GV && klo == GL) ? lane : 0;
            int wl       = (int)redux_max((unsigned)winner);

            float wx, wy;
            upk2(wx, wy, kxy);
            float nsx = __shfl_sync(0xffffffffu, wx, wl);
            float nsy = __shfl_sync(0xffffffffu, wy, wl);
            float nsz = __shfl_sync(0xffffffffu, kz, wl);

            if (lane == 0) {
                s.bc[0] = nsx; s.bc[1] = nsy; s.bc[2] = nsz;
                if (cta == 0) {
                    float* o = out + ((size_t)b * NSAMP + it) * 3;
                    o[0] = nsx; o[1] = nsy; o[2] = nsz;
                }
            }
        }
        __syncthreads();
        sx = s.bc[0]; sy = s.bc[1]; sz = s.bc[2];
    }
}

extern "C" void kernel_launch(void* const* d_in, const int* in_sizes, int n_in,
                              void* d_out, int out_size)
{
    (void)in_sizes; (void)n_in; (void)out_size;
    const float* pc  = (const float*)d_in[0];
    float*       out = (float*)d_out;

    static bool attr_set = false;
    if (!attr_set) {
        cudaFuncSetAttribute(fps_kernel,
                             cudaFuncAttributeMaxDynamicSharedMemorySize,
                             (int)sizeof(Smem));
        attr_set = true;
    }
    fps_kernel<<<NBATCH * CPB, THREADS, sizeof(Smem)>>>(pc, out);
}

// round 14
// speedup vs baseline: 1.3938x; 1.3938x over previous
#include <cuda_runtime.h>
#include <cstdint>

// FPS B=16, N=65536, S=2048, out = coords of selected (B,S,3) f32.
// R14 = R9 (champion, 3504us) with the mbarrier exchange replaced by direct
// DSMEM tag polling: writers push {key, coords} then st.release.cluster an
// iteration tag; readers spin on local tags with ld.acquire.cluster (LDS
// speed, no TRYWAIT wakeup), then tree-scan 8 contiguous keys and load only
// the winner's coords. Parity double-buffering (max cluster skew = 1 iter);
// monotonic tags (it+1), no resets. Hot loop / reductions identical to R9.

#define NBATCH   16
#define NPTS     65536
#define NSAMP    2048
#define CLUSTER  8
#define NPC      (NPTS / CLUSTER)     // 8192
#define THREADS  512
#define NWARPS   (THREADS / 32)       // 16
#define PPT      (NPC / THREADS)      // 16
#define GROUPS   (PPT / 4)            // 4

typedef unsigned long long u64;

struct __align__(16) Smem {
    float    x[NPC];              // negated coords
    float    y[NPC];
    float    z[NPC];
    u64      wkey[NWARPS];        // per-warp packed (valBits<<32)|~localIdx
    u64      keys[2][CLUSTER];    // exchange keys, contiguous (2x LDS.128 scan)
    ulonglong2 coords[2][CLUSTER];// {xy packed, z packed in .x of pair}
    unsigned tags[2][CLUSTER];    // iteration tags, written last w/ release
};

__device__ __forceinline__ uint32_t smem_u32(const void* p) {
    return (uint32_t)__cvta_generic_to_shared(p);
}
__device__ __forceinline__ u64 pk2(float lo, float hi) {
    u64 r; asm("mov.b64 %0, {%1, %2};" : "=l"(r) : "f"(lo), "f"(hi)); return r;
}
__device__ __forceinline__ void upk2(float& lo, float& hi, u64 v) {
    asm("mov.b64 {%0, %1}, %2;" : "=f"(lo), "=f"(hi) : "l"(v));
}
__device__ __forceinline__ u64 add2(u64 a, u64 b) {
    u64 r; asm("add.rn.f32x2 %0, %1, %2;" : "=l"(r) : "l"(a), "l"(b)); return r;
}
__device__ __forceinline__ u64 mul2(u64 a, u64 b) {
    u64 r; asm("mul.rn.f32x2 %0, %1, %2;" : "=l"(r) : "l"(a), "l"(b)); return r;
}
__device__ __forceinline__ unsigned redux_max(unsigned v) {
    unsigned r; asm("redux.sync.max.u32 %0, %1, 0xffffffff;" : "=r"(r) : "r"(v)); return r;
}
__device__ __forceinline__ unsigned redux_min(unsigned v) {
    unsigned r; asm("redux.sync.min.u32 %0, %1, 0xffffffff;" : "=r"(r) : "r"(v)); return r;
}

__global__ void __cluster_dims__(CLUSTER, 1, 1) __launch_bounds__(THREADS, 2)
fps_kernel(const float* __restrict__ pc, float* __restrict__ out)
{
    extern __shared__ char smraw[];
    Smem& s = *reinterpret_cast<Smem*>(smraw);

    const int tid  = threadIdx.x;
    const int lane = tid & 31;
    const int warp = tid >> 5;
    const int rank = blockIdx.x & (CLUSTER - 1);
    const int b    = blockIdx.x >> 3;

    const float* __restrict__ base = pc + (size_t)b * NPTS * 3;

    // ---- prologue: stage NEGATED coords as SoA; zero tags ----
    for (int i = tid; i < NPC; i += THREADS) {
        int gi = rank * NPC + i;
        s.x[i] = -base[gi * 3 + 0];
        s.y[i] = -base[gi * 3 + 1];
        s.z[i] = -base[gi * 3 + 2];
    }
    if (tid < 2 * CLUSTER) s.tags[tid >> 3][tid & 7] = 0u;

    float closest[PPT];
    #pragma unroll
    for (int i = 0; i < PPT; i++) closest[i] = __int_as_float(0x7f800000);

    float sx = base[0], sy = base[1], sz = base[2];   // initial selection: point 0

    __syncthreads();
    asm volatile("barrier.cluster.arrive.aligned;" ::: "memory");
    asm volatile("barrier.cluster.wait.aligned;"   ::: "memory");

    for (int it = 0; it < NSAMP; ++it) {
        const int p = it & 1;
        const unsigned want = (unsigned)(it + 1);

        u64 sxx = pk2(sx, sx), syy = pk2(sy, sy), szz = pk2(sz, sz);

        // ---- distance update + running min; value-only max (packed f32x2) ----
        float vmax = 0.0f;
        #pragma unroll
        for (int g = 0; g < GROUPS; ++g) {
            const int bi = g * (THREADS * 4) + tid * 4;
            ulonglong2 X = *reinterpret_cast<const ulonglong2*>(&s.x[bi]);
            ulonglong2 Y = *reinterpret_cast<const ulonglong2*>(&s.y[bi]);
            ulonglong2 Z = *reinterpret_cast<const ulonglong2*>(&s.z[bi]);
            {   // points 0,1 : d = (s + (-x))^2 + (s + (-y))^2 + (s + (-z))^2
                u64 dx = add2(sxx, X.x);
                u64 dy = add2(syy, Y.x);
                u64 dz = add2(szz, Z.x);
                u64 d  = add2(add2(mul2(dx, dx), mul2(dy, dy)), mul2(dz, dz));
                float d0, d1; upk2(d0, d1, d);
                float c0 = fminf(closest[g*4+0], d0); closest[g*4+0] = c0;
                float c1 = fminf(closest[g*4+1], d1); closest[g*4+1] = c1;
                vmax = fmaxf(vmax, c0); vmax = fmaxf(vmax, c1);
            }
            {   // points 2,3
                u64 dx = add2(sxx, X.y);
                u64 dy = add2(syy, Y.y);
                u64 dz = add2(szz, Z.y);
                u64 d  = add2(add2(mul2(dx, dx), mul2(dy, dy)), mul2(dz, dz));
                float d0, d1; upk2(d0, d1, d);
                float c0 = fminf(closest[g*4+2], d0); closest[g*4+2] = c0;
                float c1 = fminf(closest[g*4+3], d1); closest[g*4+3] = c1;
                vmax = fmaxf(vmax, c0); vmax = fmaxf(vmax, c1);
            }
        }

        // ---- warp reduce: value max + exact first local index ----
        const unsigned wmax = redux_max(__float_as_uint(vmax));
        unsigned my = 0xffffffffu;
        #pragma unroll
        for (int g = 0; g < GROUPS; ++g) {
            #pragma unroll
            for (int j = 0; j < 4; ++j) {
                unsigned cand = (unsigned)(g * (THREADS * 4) + tid * 4 + j);
                if (__float_as_uint(closest[g*4+j]) == wmax)
                    my = (cand < my) ? cand : my;
            }
        }
        const unsigned wmin = redux_min(my);
        if (lane == 0)
            s.wkey[warp] = ((u64)wmax << 32) | (u64)(unsigned)(~wmin);
        __syncthreads();

        // ---- warp 0: CTA reduce (split-u32 redux) + push key/coords/tag ----
        if (warp == 0) {
            u64 wk = (lane < NWARPS) ? s.wkey[lane] : 0ull;
            unsigned vhi = (unsigned)(wk >> 32);
            unsigned vlo = (unsigned)wk;                          // ~localIdx
            unsigned Vmax = redux_max(vhi);
            unsigned nli  = redux_max((vhi == Vmax) ? vlo : 0u);  // max ~idx = min idx
            if (lane < CLUSTER) {
                unsigned li   = ~nli;
                unsigned gidx = (unsigned)rank * NPC + li;
                u64 ckey = ((u64)Vmax << 32) | (u64)(unsigned)(~gidx);
                float cx = -s.x[li], cy = -s.y[li], cz = -s.z[li];   // un-negate
                u64 xy = pk2(cx, cy);
                u64 zp = pk2(cz, 0.0f);
                uint32_t ak = smem_u32(&s.keys[p][rank]);
                uint32_t ac = smem_u32(&s.coords[p][rank]);
                uint32_t at = smem_u32(&s.tags[p][rank]);
                uint32_t rk, rc, rt;
                asm volatile("mapa.shared::cluster.u32 %0, %1, %2;" : "=r"(rk) : "r"(ak), "r"(lane));
                asm volatile("mapa.shared::cluster.u32 %0, %1, %2;" : "=r"(rc) : "r"(ac), "r"(lane));
                asm volatile("mapa.shared::cluster.u32 %0, %1, %2;" : "=r"(rt) : "r"(at), "r"(lane));
                asm volatile("st.shared::cluster.b64 [%0], %1;" :: "r"(rk), "l"(ckey) : "memory");
                asm volatile("st.shared::cluster.v2.b64 [%0], {%1, %2};"
                             :: "r"(rc), "l"(xy), "l"(zp) : "memory");
                asm volatile("st.release.cluster.shared::cluster.b32 [%0], %1;"
                             :: "r"(rt), "r"(want) : "memory");
            }
        }

        // ---- every warp: lanes 0..7 spin on local tags, then all scan ----
        if (lane < CLUSTER) {
            unsigned t;
            const uint32_t ta = smem_u32(&s.tags[p][lane]);
            do {
                asm volatile("ld.acquire.cluster.shared::cta.b32 %0, [%1];"
                             : "=r"(t) : "r"(ta) : "memory");
            } while (t != want);
        }
        __syncwarp();

        // tree-scan 8 contiguous keys (2x LDS.128), track winner index
        const u64* kp = s.keys[p];
        ulonglong2 k01 = *reinterpret_cast<const ulonglong2*>(&kp[0]);
        ulonglong2 k23 = *reinterpret_cast<const ulonglong2*>(&kp[2]);
        ulonglong2 k45 = *reinterpret_cast<const ulonglong2*>(&kp[4]);
        ulonglong2 k67 = *reinterpret_cast<const ulonglong2*>(&kp[6]);
        u64 kA = k01.x; int iA = 0;  if (k01.y > kA) { kA = k01.y; iA = 1; }
        u64 kB = k23.x; int iB = 2;  if (k23.y > kB) { kB = k23.y; iB = 3; }
        u64 kC = k45.x; int iC = 4;  if (k45.y > kC) { kC = k45.y; iC = 5; }
        u64 kD = k67.x; int iD = 6;  if (k67.y > kD) { kD = k67.y; iD = 7; }
        if (kB > kA) { kA = kB; iA = iB; }
        if (kD > kC) { kC = kD; iC = iD; }
        if (kC > kA) { kA = kC; iA = iC; }

        ulonglong2 wcoord = s.coords[p][iA];
        float nsx, nsy, nsz, dummy;
        upk2(nsx, nsy, wcoord.x);
        upk2(nsz, dummy, wcoord.y);

        if (rank == 0 && tid == 0) {
            float* o = out + ((size_t)b * NSAMP + it) * 3;
            o[0] = nsx; o[1] = nsy; o[2] = nsz;
        }
        sx = nsx; sy = nsy; sz = nsz;
    }
}

extern "C" void kernel_launch(void* const* d_in, const int* in_sizes, int n_in,
                              void* d_out, int out_size)
{
    (void)in_sizes; (void)n_in; (void)out_size;
    const float* pc  = (const float*)d_in[0];
    float*       out = (float*)d_out;

    static bool attr_set = false;
    if (!attr_set) {
        cudaFuncSetAttribute(fps_kernel,
                             cudaFuncAttributeMaxDynamicSharedMemorySize,
                             (int)sizeof(Smem));
        attr_set = true;
    }

    cudaLaunchConfig_t cfg = {};
    cfg.gridDim = dim3(NBATCH * CLUSTER, 1, 1);
    cfg.blockDim = dim3(THREADS, 1, 1);
    cfg.dynamicSmemBytes = sizeof(Smem);
    cfg.stream = 0;
    cudaLaunchAttribute attrs[1];
    attrs[0].id = cudaLaunchAttributeClusterDimension;
    attrs[0].val.clusterDim = {CLUSTER, 1, 1};
    cfg.attrs = attrs;
    cfg.numAttrs = 1;
    cudaLaunchKernelEx(&cfg, fps_kernel, pc, out);
}

// round 15
// speedup vs baseline: 1.6746x; 1.2015x over previous
#include <cuda_runtime.h>
#include <cstdint>

// FPS B=16, N=65536, S=2048, out = coords of selected (B,S,3) f32.
// R15 = R9 (champion, 3504us) with ONE isolated change: only warp 0 waits on
// the cluster mbarrier and scans the 8 exchange slots; warps 1-15 wait at a
// cheap block barrier and read the winner from a smem broadcast cell. Tests
// the hypothesis that 16-warp mbarrier wakeup is serialized (~60cyc/warp).
// Hot loop / reductions / push protocol byte-identical to R9.

#define NBATCH   16
#define NPTS     65536
#define NSAMP    2048
#define CLUSTER  8
#define NPC      (NPTS / CLUSTER)     // 8192
#define THREADS  512
#define NWARPS   (THREADS / 32)       // 16
#define PPT      (NPC / THREADS)      // 16
#define GROUPS   (PPT / 4)            // 4

typedef unsigned long long u64;

// 32-byte slot: key @0 (16-aligned), xy packed @8, z @16.
struct __align__(16) Slot { u64 key; u64 xy; float z; float pad[3]; };

struct __align__(16) Smem {
    float x[NPC];                // negated coords
    float y[NPC];
    float z[NPC];
    u64   wkey[NWARPS];          // per-warp packed (valBits<<32)|~localIdx
    Slot  slots[2][CLUSTER];     // parity-double-buffered cluster exchange
    u64   mbar;
    float bc[4];                 // broadcast: winner coords (BAR-ordered)
};

__device__ __forceinline__ uint32_t smem_u32(const void* p) {
    return (uint32_t)__cvta_generic_to_shared(p);
}
__device__ __forceinline__ u64 pk2(float lo, float hi) {
    u64 r; asm("mov.b64 %0, {%1, %2};" : "=l"(r) : "f"(lo), "f"(hi)); return r;
}
__device__ __forceinline__ void upk2(float& lo, float& hi, u64 v) {
    asm("mov.b64 {%0, %1}, %2;" : "=f"(lo), "=f"(hi) : "l"(v));
}
__device__ __forceinline__ u64 add2(u64 a, u64 b) {
    u64 r; asm("add.rn.f32x2 %0, %1, %2;" : "=l"(r) : "l"(a), "l"(b)); return r;
}
__device__ __forceinline__ u64 mul2(u64 a, u64 b) {
    u64 r; asm("mul.rn.f32x2 %0, %1, %2;" : "=l"(r) : "l"(a), "l"(b)); return r;
}
__device__ __forceinline__ unsigned redux_max(unsigned v) {
    unsigned r; asm("redux.sync.max.u32 %0, %1, 0xffffffff;" : "=r"(r) : "r"(v)); return r;
}
__device__ __forceinline__ unsigned redux_min(unsigned v) {
    unsigned r; asm("redux.sync.min.u32 %0, %1, 0xffffffff;" : "=r"(r) : "r"(v)); return r;
}

__global__ void __launch_bounds__(THREADS, 2)
fps_kernel(const float* __restrict__ pc, float* __restrict__ out)
{
    extern __shared__ char smraw[];
    Smem& s = *reinterpret_cast<Smem*>(smraw);

    const int tid  = threadIdx.x;
    const int lane = tid & 31;
    const int warp = tid >> 5;
    const int rank = blockIdx.x & (CLUSTER - 1);
    const int b    = blockIdx.x >> 3;

    const float* __restrict__ base = pc + (size_t)b * NPTS * 3;

    // ---- prologue: stage NEGATED coords as SoA ----
    for (int i = tid; i < NPC; i += THREADS) {
        int gi = rank * NPC + i;
        s.x[i] = -base[gi * 3 + 0];
        s.y[i] = -base[gi * 3 + 1];
        s.z[i] = -base[gi * 3 + 2];
    }
    if (tid == 0) {
        asm volatile("mbarrier.init.shared.b64 [%0], %1;"
                     :: "r"(smem_u32(&s.mbar)), "r"(CLUSTER) : "memory");
    }

    float closest[PPT];
    #pragma unroll
    for (int i = 0; i < PPT; i++) closest[i] = __int_as_float(0x7f800000);

    float sx = base[0], sy = base[1], sz = base[2];   // initial selection: point 0

    __syncthreads();
    asm volatile("barrier.cluster.arrive.aligned;" ::: "memory");
    asm volatile("barrier.cluster.wait.aligned;"   ::: "memory");

    const uint32_t mb_addr = smem_u32(&s.mbar);

    for (int it = 0; it < NSAMP; ++it) {
        const int p = it & 1;

        u64 sxx = pk2(sx, sx), syy = pk2(sy, sy), szz = pk2(sz, sz);

        // ---- distance update + running min; value-only max (packed f32x2) ----
        float vmax = 0.0f;
        #pragma unroll
        for (int g = 0; g < GROUPS; ++g) {
            const int bi = g * (THREADS * 4) + tid * 4;
            ulonglong2 X = *reinterpret_cast<const ulonglong2*>(&s.x[bi]);
            ulonglong2 Y = *reinterpret_cast<const ulonglong2*>(&s.y[bi]);
            ulonglong2 Z = *reinterpret_cast<const ulonglong2*>(&s.z[bi]);
            {   // points 0,1 : d = (s + (-x))^2 + (s + (-y))^2 + (s + (-z))^2
                u64 dx = add2(sxx, X.x);
                u64 dy = add2(syy, Y.x);
                u64 dz = add2(szz, Z.x);
                u64 d  = add2(add2(mul2(dx, dx), mul2(dy, dy)), mul2(dz, dz));
                float d0, d1; upk2(d0, d1, d);
                float c0 = fminf(closest[g*4+0], d0); closest[g*4+0] = c0;
                float c1 = fminf(closest[g*4+1], d1); closest[g*4+1] = c1;
                vmax = fmaxf(vmax, c0); vmax = fmaxf(vmax, c1);
            }
            {   // points 2,3
                u64 dx = add2(sxx, X.y);
                u64 dy = add2(syy, Y.y);
                u64 dz = add2(szz, Z.y);
                u64 d  = add2(add2(mul2(dx, dx), mul2(dy, dy)), mul2(dz, dz));
                float d0, d1; upk2(d0, d1, d);
                float c0 = fminf(closest[g*4+2], d0); closest[g*4+2] = c0;
                float c1 = fminf(closest[g*4+3], d1); closest[g*4+3] = c1;
                vmax = fmaxf(vmax, c0); vmax = fmaxf(vmax, c1);
            }
        }

        // ---- warp reduce: redux max on float bits (all >= 0) ----
        const unsigned wmax = redux_max(__float_as_uint(vmax));

        // exact first index: parallel min over matching indices
        unsigned my = 0xffffffffu;
        #pragma unroll
        for (int g = 0; g < GROUPS; ++g) {
            #pragma unroll
            for (int j = 0; j < 4; ++j) {
                unsigned cand = (unsigned)(g * (THREADS * 4) + tid * 4 + j);
                if (__float_as_uint(closest[g*4+j]) == wmax)
                    my = (cand < my) ? cand : my;
            }
        }
        const unsigned wmin = redux_min(my);
        if (lane == 0)
            s.wkey[warp] = ((u64)wmax << 32) | (u64)(unsigned)(~wmin);
        __syncthreads();                                   // BAR1: wkey visible

        // ---- warp 0: CTA reduce (split-u32 redux) + push + wait + scan ----
        if (warp == 0) {
            u64 wk = (lane < NWARPS) ? s.wkey[lane] : 0ull;
            unsigned vhi = (unsigned)(wk >> 32);
            unsigned vlo = (unsigned)wk;                       // ~localIdx
            unsigned Vmax = redux_max(vhi);
            unsigned nli  = redux_max((vhi == Vmax) ? vlo : 0u);  // max ~idx = min idx
            if (lane < CLUSTER) {
                unsigned li   = ~nli;
                unsigned gidx = (unsigned)rank * NPC + li;
                u64 ckey = ((u64)Vmax << 32) | (u64)(unsigned)(~gidx);
                float cx = -s.x[li], cy = -s.y[li], cz = -s.z[li];   // un-negate
                u64 xy = pk2(cx, cy);
                uint32_t sl = smem_u32(&s.slots[p][rank]);
                uint32_t rs, rb;
                asm volatile("mapa.shared::cluster.u32 %0, %1, %2;" : "=r"(rs) : "r"(sl),      "r"(lane));
                asm volatile("mapa.shared::cluster.u32 %0, %1, %2;" : "=r"(rb) : "r"(mb_addr), "r"(lane));
                asm volatile("st.shared::cluster.v2.b64 [%0], {%1, %2};"
                             :: "r"(rs), "l"(ckey), "l"(xy) : "memory");
                asm volatile("st.shared::cluster.f32 [%0+16], %1;" :: "r"(rs), "f"(cz) : "memory");
                asm volatile("mbarrier.arrive.release.cluster.shared::cluster.b64 _, [%0];"
                             :: "r"(rb) : "memory");
            }

            // ONLY warp 0 waits on the mbarrier (single-warp wakeup)
            asm volatile(
                "{\n\t.reg .pred P;\n"
                "W%=:\n\t"
                "mbarrier.try_wait.parity.acquire.cluster.shared::cta.b64 P, [%0], %1, 0x989680;\n\t"
                "@P bra.uni D%=;\n\t"
                "bra.uni W%=;\n"
                "D%=:\n\t}"
                :: "r"(mb_addr), "r"(p) : "memory");

            // scan 8 local slots; write winner coords to broadcast cell
            const Slot* sl = s.slots[p];
            u64 bk = sl[0].key;
            int br = 0;
            #pragma unroll
            for (int r = 1; r < CLUSTER; ++r) {
                u64 kr = sl[r].key;
                if (kr > bk) { bk = kr; br = r; }
            }
            float nsx, nsy;
            upk2(nsx, nsy, sl[br].xy);
            float nsz = sl[br].z;
            if (lane == 0) {
                s.bc[0] = nsx; s.bc[1] = nsy; s.bc[2] = nsz;
                if (rank == 0) {
                    float* o = out + ((size_t)b * NSAMP + it) * 3;
                    o[0] = nsx; o[1] = nsy; o[2] = nsz;
                }
            }
        }
        __syncthreads();                                   // BAR2: bc visible
        sx = s.bc[0]; sy = s.bc[1]; sz = s.bc[2];
    }
}

extern "C" void kernel_launch(void* const* d_in, const int* in_sizes, int n_in,
                              void* d_out, int out_size)
{
    (void)in_sizes; (void)n_in; (void)out_size;
    const float* pc  = (const float*)d_in[0];
    float*       out = (float*)d_out;

    static bool attr_set = false;
    if (!attr_set) {
        cudaFuncSetAttribute(fps_kernel,
                             cudaFuncAttributeMaxDynamicSharedMemorySize,
                             (int)sizeof(Smem));
        attr_set = true;
    }

    cudaLaunchConfig_t cfg = {};
    cfg.gridDim = dim3(NBATCH * CLUSTER, 1, 1);
    cfg.blockDim = dim3(THREADS, 1, 1);
    cfg.dynamicSmemBytes = sizeof(Smem);
    cfg.stream = 0;
    cudaLaunchAttribute attrs[1];
    attrs[0].id = cudaLaunchAttributeClusterDimension;
    attrs[0].val.clusterDim = {CLUSTER, 1, 1};
    cfg.attrs = attrs;
    cfg.numAttrs = 1;
    cudaLaunchKernelEx(&cfg, fps_kernel, pc, out);
}